// round 5
// baseline (speedup 1.0000x reference)
#include <cuda_runtime.h>
#include <cstdint>

#define NB 64
#define NT 256
#define NC 2048
#define NH 512
#define NO 11
#define THRESH 1.0f
#define LEAKV  0.003f
#define OLEAK  0.0015f

// Scratch (static device allocations — allowed)
__device__ float g_Iin[NB * NT * NH];      // [b][t][h] = x @ w1^T
__device__ float g_WrecT[NH * NH];         // [j][h] = w_rec[h][j]

typedef unsigned long long ull;

// Packed fp32x2 FMA: two independent IEEE fp32 fma.rn per instruction (FFMA2).
__device__ __forceinline__ void fma2(ull& d, ull a, ull b) {
    asm("fma.rn.f32x2 %0, %1, %2, %0;" : "+l"(d) : "l"(a), "l"(b));
}
__device__ __forceinline__ ull dup_f32(float v) {
    unsigned u = __float_as_uint(v);
    return (ull)u | ((ull)u << 32);
}

// ---------------------------------------------------------------------------
// Prep: transpose w_rec
// ---------------------------------------------------------------------------
__global__ void prep_kernel(const float* __restrict__ w_rec) {
    int idx = blockIdx.x * blockDim.x + threadIdx.x;
    if (idx < NH * NH) {
        int h = idx / NH, j = idx % NH;
        g_WrecT[j * NH + h] = w_rec[idx];
    }
}

// ---------------------------------------------------------------------------
// fp32 GEMM via packed FFMA2, BIT-EXACT to the R1 SIMT kernel:
// every output element accumulates af[m]*bf[n] with one fma.rn per k,
// k ascending 0..2047 — identical order, identical values.
// Iin[M,N] = x[M,K] @ w1[N,K]^T ; M=16384, N=512, K=2048.
// 128x128 CTA tile, BK=8, 256 threads, 8x8 outputs/thread (as 8x4 f32x2 pairs).
// A is stored duplicated in smem ({a,a}) so the broadcast operand is one LDS.128.
// Double-buffered with register prefetch: one __syncthreads per chunk.
// ---------------------------------------------------------------------------
#define BM 128
#define BN 128
#define BKK 8
#define ADSTRIDE 260   // floats; 1040 B rows, 16B-aligned
#define BSTRIDE  136

__global__ __launch_bounds__(256, 2) void gemm_kernel(
    const float* __restrict__ A,    // x  [M,K]
    const float* __restrict__ W)    // w1 [N,K]
{
    const int K = NC;
    __shared__ __align__(16) float sAd[2][BKK][ADSTRIDE];  // duplicated A pairs
    __shared__ __align__(16) float sB [2][BKK][BSTRIDE];

    const int tid  = threadIdx.x;
    const int trow = tid / 16;          // 0..15
    const int tcol = tid % 16;          // 0..15
    const int lrow = tid >> 1;          // 0..127
    const int lcol = (tid & 1) * 4;     // 0 or 4

    const float* Ab = A + (size_t)blockIdx.y * BM * K + (size_t)lrow * K + lcol;
    const float* Wb = W + (size_t)blockIdx.x * BN * K + (size_t)lrow * K + lcol;

    ull acc[8][4];
    #pragma unroll
    for (int m = 0; m < 8; ++m)
        #pragma unroll
        for (int p = 0; p < 4; ++p) acc[m][p] = 0ull;

    float4 av, wv;

    // Prologue: load + stage chunk 0
    av = *(const float4*)(Ab);
    wv = *(const float4*)(Wb);
    {
        float ae[4] = {av.x, av.y, av.z, av.w};
        float we[4] = {wv.x, wv.y, wv.z, wv.w};
        #pragma unroll
        for (int e = 0; e < 4; ++e) {
            *(ull*)&sAd[0][lcol + e][2 * lrow] = dup_f32(ae[e]);
            sB[0][lcol + e][lrow] = we[e];
        }
    }
    __syncthreads();

    const int NITER = K / BKK;   // 256
    for (int kc = 0; kc < NITER; ++kc) {
        const int cur = kc & 1;
        const int nxt = cur ^ 1;

        // Register prefetch of next chunk
        if (kc + 1 < NITER) {
            av = *(const float4*)(Ab + (kc + 1) * BKK);
            wv = *(const float4*)(Wb + (kc + 1) * BKK);
        }

        // Compute current chunk: k ascending, one FFMA2 per output pair per k.
        #pragma unroll
        for (int k = 0; k < BKK; ++k) {
            ulonglong2 a01 = *(const ulonglong2*)&sAd[cur][k][trow * 16 + 0];
            ulonglong2 a23 = *(const ulonglong2*)&sAd[cur][k][trow * 16 + 4];
            ulonglong2 a45 = *(const ulonglong2*)&sAd[cur][k][trow * 16 + 8];
            ulonglong2 a67 = *(const ulonglong2*)&sAd[cur][k][trow * 16 + 12];
            ulonglong2 b01 = *(const ulonglong2*)&sB[cur][k][tcol * 8 + 0];
            ulonglong2 b23 = *(const ulonglong2*)&sB[cur][k][tcol * 8 + 4];
            ull af[8] = { a01.x, a01.y, a23.x, a23.y, a45.x, a45.y, a67.x, a67.y };
            ull bf[4] = { b01.x, b01.y, b23.x, b23.y };
            #pragma unroll
            for (int m = 0; m < 8; ++m) {
                fma2(acc[m][0], af[m], bf[0]);
                fma2(acc[m][1], af[m], bf[1]);
                fma2(acc[m][2], af[m], bf[2]);
                fma2(acc[m][3], af[m], bf[3]);
            }
        }

        // Stage next chunk into the other buffer
        if (kc + 1 < NITER) {
            float ae[4] = {av.x, av.y, av.z, av.w};
            float we[4] = {wv.x, wv.y, wv.z, wv.w};
            #pragma unroll
            for (int e = 0; e < 4; ++e) {
                *(ull*)&sAd[nxt][lcol + e][2 * lrow] = dup_f32(ae[e]);
                sB[nxt][lcol + e][lrow] = we[e];
            }
            __syncthreads();
        }
    }

    // Epilogue: identical addresses/values to R1 (float4 stores of n..n+3)
    float* Cb = g_Iin + ((size_t)blockIdx.y * BM + trow * 8) * NH
                      + blockIdx.x * BN + tcol * 8;
    #pragma unroll
    for (int m = 0; m < 8; ++m) {
        *(ulonglong2*)(Cb + (size_t)m * NH + 0) = make_ulonglong2(acc[m][0], acc[m][1]);
        *(ulonglong2*)(Cb + (size_t)m * NH + 4) = make_ulonglong2(acc[m][2], acc[m][3]);
    }
}

// ---------------------------------------------------------------------------
// Sequential SNN (unchanged, known-good): one CTA / batch, 1 thread / neuron.
// ---------------------------------------------------------------------------
__global__ __launch_bounds__(512) void snn_kernel(
    const float* __restrict__ w2,   // [O,H]
    float* __restrict__ out)        // [B,O]
{
    const int b    = blockIdx.x;
    const int h    = threadIdx.x;
    const int lane = h & 31;
    const int warp = h >> 5;

    __shared__ int   s_list[NH];
    __shared__ int   s_wcnt[16];
    __shared__ int   s_base[16];
    __shared__ int   s_total;
    __shared__ float s_w2t[NH * 12];

    #pragma unroll
    for (int o = 0; o < NO; ++o)
        s_w2t[h * 12 + o] = w2[o * NH + h];

    float v1 = 0.f, rec = 0.f, v2 = 0.f, osum = 0.f;
    const float* Iin_b = g_Iin + (size_t)b * NT * NH + h;

    __syncthreads();
    float iin = Iin_b[0];

    for (int t = 0; t < NT; ++t) {
        v1 += iin + rec - LEAKV;
        bool spike = (v1 >= THRESH);
        if (spike) v1 -= THRESH;

        unsigned m = __ballot_sync(0xffffffffu, spike);
        if (lane == 0) s_wcnt[warp] = __popc(m);
        __syncthreads();
        if (h == 0) {
            int s = 0;
            #pragma unroll
            for (int w = 0; w < 16; ++w) { s_base[w] = s; s += s_wcnt[w]; }
            s_total = s;
        }
        __syncthreads();
        if (spike)
            s_list[s_base[warp] + __popc(m & ((1u << lane) - 1u))] = h;
        __syncthreads();

        const int total = s_total;
        if (t + 1 < NT) iin = Iin_b[(size_t)(t + 1) * NH];

        rec = 0.f;
        #pragma unroll 4
        for (int i = 0; i < total; ++i)
            rec += g_WrecT[s_list[i] * NH + h];

        if (h < NO) {
            float i2 = 0.f;
            #pragma unroll 4
            for (int i = 0; i < total; ++i)
                i2 += s_w2t[s_list[i] * 12 + h];
            v2 = fmaxf(v2 + i2 - OLEAK, 0.f);
            osum += v2;
        }
        __syncthreads();
    }

    if (h < NO) out[b * NO + h] = osum * (1.0f / (float)NT);
}

// ---------------------------------------------------------------------------
extern "C" void kernel_launch(void* const* d_in, const int* in_sizes, int n_in,
                              void* d_out, int out_size) {
    const float* x     = (const float*)d_in[0];
    const float* w1    = (const float*)d_in[1];
    const float* w_rec = (const float*)d_in[2];
    const float* w2    = (const float*)d_in[3];
    float* out = (float*)d_out;

    prep_kernel<<<(NH * NH + 255) / 256, 256>>>(w_rec);

    dim3 gg(NH / BN, (NB * NT) / BM);   // (4, 128)
    gemm_kernel<<<gg, 256>>>(x, w1);

    snn_kernel<<<NB, NH>>>(w2, out);
}